// round 9
// baseline (speedup 1.0000x reference)
#include <cuda_runtime.h>

typedef unsigned long long ull;
typedef unsigned int uint;

namespace {
constexpr int H = 512;
constexpr int B = 64;
constexpr int T = 1000;
constexpr int NWORK = 128;
constexpr int NCTA = NWORK + 1;
constexpr int NT = 256;
constexpr int WSM_BYTES = 24 * H * 4;          // 49152: 24 rows x 512 f32 k-packed
constexpr int RED_OFF = WSM_BYTES;             // 12*512 floats = 24576
constexpr int FLG_OFF = RED_OFF + 24576;       // 73728
constexpr unsigned SMEM_BYTES = FLG_OFF + 64;  // 73792
}

__device__ float g_x[2][H * B];   // swizzled tiled layout, see G()
__device__ float g_h0[H * B];
__device__ uint g_flags[NCTA];    // workers: phase|sticky<<16; [128]: output phase
__device__ uint g_tconv = 0x7FFFFFFFu;
__device__ uint g_count = 0;
__device__ uint g_gen = 0;

__device__ __forceinline__ ull fma2(ull a, ull b, ull c) {
    ull d; asm("fma.rn.f32x2 %0, %1, %2, %3;" : "=l"(d) : "l"(a), "l"(b), "l"(c));
    return d;
}
__device__ __forceinline__ void unpack2(ull v, float& lo, float& hi) {
    asm("mov.b64 {%0, %1}, %2;" : "=f"(lo), "=f"(hi) : "l"(v));
}
__device__ __forceinline__ float sigm(float x) {
    return __fdividef(1.0f, 1.0f + __expf(-x));
}
__device__ __forceinline__ float tanh_(float x) {
    return __fmaf_rn(2.0f, sigm(x + x), -1.0f);
}

// Bank swizzle of the batch index within its 8-group.
__device__ __forceinline__ int sw16(int b) {
    return (b & 56) | ((b ^ (b >> 3)) & 7);
}
// Global float index of h[col c][batch b], tiled [k/4][swiz(b)][k%4].
__device__ __forceinline__ int G(int b, int c) {
    return ((c >> 2) << 8) + (sw16(b) << 2) + (c & 3);
}

__device__ __forceinline__ uint ldacq(const uint* a) {
    uint f;
    asm volatile("ld.acquire.gpu.u32 %0, [%1];" : "=r"(f) : "l"(a) : "memory");
    return f;
}
__device__ __forceinline__ void publish(uint* addr, uint v) {
    asm volatile("st.release.gpu.u32 [%0], %1;" :: "l"(addr), "r"(v) : "memory");
}

// Warp 0 (and output CTA): full 128-flag poll, 4 parallel loads/lane (+output
// flag on lane 0). Writes OR of sticky bits to *spub (lane 0).
__device__ __forceinline__ void poll_full(uint ph, uint* spub) {
    const uint* a = &g_flags[threadIdx.x & 31];
    bool lane0 = ((threadIdx.x & 31) == 0);
    uint f0, f1, f2, f3, f4;
    for (;;) {
        f0 = ldacq(a); f1 = ldacq(a + 32); f2 = ldacq(a + 64); f3 = ldacq(a + 96);
        f4 = lane0 ? ldacq(&g_flags[NWORK]) : 0xFFFFu;
        if ((f0 & 0xFFFFu) >= ph && (f1 & 0xFFFFu) >= ph &&
            (f2 & 0xFFFFu) >= ph && (f3 & 0xFFFFu) >= ph &&
            (f4 & 0xFFFFu) >= ph) break;
    }
    uint any = (f0 >> 16) | (f1 >> 16) | (f2 >> 16) | (f3 >> 16);
    uint r = __any_sync(0xFFFFFFFFu, any != 0u);
    if (lane0) *spub = r;
}

// Warps 1..7: poll only the 16 producer CTAs of this warp's k-chunk.
__device__ __forceinline__ void poll_16(int e) {
    const uint* a = &g_flags[e * 16 + (threadIdx.x & 15)];
    // ph passed via caller loop below
    (void)a;
}

__device__ __forceinline__ void warp_poll16(int e, uint ph) {
    const uint* a = &g_flags[e * 16 + (threadIdx.x & 15)];
    for (;;) {
        uint f = ldacq(a);
        if (__all_sync(0xFFFFFFFFu, (f & 0xFFFFu) >= ph)) break;
    }
}

__device__ __forceinline__ void final_barrier() {
    __syncthreads();
    if (threadIdx.x == 0) {
        uint snap, old;
        asm volatile("ld.acquire.gpu.u32 %0, [%1];" : "=r"(snap) : "l"(&g_gen) : "memory");
        asm volatile("atom.add.release.gpu.u32 %0, [%1], %2;"
                     : "=r"(old) : "l"(&g_count), "r"(1u) : "memory");
        if (old == NCTA - 1) {
            asm volatile("st.relaxed.gpu.u32 [%0], %1;" :: "l"(&g_count), "r"(0u) : "memory");
            asm volatile("st.release.gpu.u32 [%0], %1;" :: "l"(&g_gen), "r"(snap + 1u) : "memory");
        } else {
            uint g;
            do {
                asm volatile("ld.acquire.gpu.u32 %0, [%1];" : "=r"(g) : "l"(&g_gen) : "memory");
            } while (g == snap);
        }
    }
    __syncthreads();
}

__global__ __launch_bounds__(NT, 1) void fhn_kernel(
    const float* u0, const float* w0, const float* Kc,
    const float* W_in, const float* b_in,
    const float* W_ih0, const float* b_ih0, const float* b_hh0,
    const float* W_ih1, const float* b_ih1, const float* b_hh1,
    const float* W_u, const float* b_u, const float* W_w, const float* b_w,
    float* out)
{
    extern __shared__ char smem[];
    ulonglong2* Wsm = (ulonglong2*)smem;        // [24 rows][128 kb] (16B = 4 k)
    float* red = (float*)(smem + RED_OFF);      // [12][8][64]
    uint* sflag = (uint*)(smem + FLG_OFF);
    uint* spub = sflag + 1;
    uint* stcv = sflag + 2;

    const int tid = threadIdx.x;
    const int cta = blockIdx.x;

    if (cta < NWORK) {
        // ========================= worker CTA =========================
        const int c0 = cta * 4;
        const int gbase[3] = {0, 2 * H, 3 * H};   // i, g, o rows (f-gate dead)

        for (int i = tid; i < 24 * 128; i += NT) {
            int r = i >> 7, kb = i & 127;
            int l = r / 12, j = r % 12;
            int g = j >> 2, cl = j & 3;
            const float4* W = (const float4*)(l ? W_ih1 : W_ih0);
            ((float4*)Wsm)[i] = W[(gbase[g] + c0 + cl) * (H / 4) + kb];
        }
        if (tid == 0) *sflag = 0u;
        const int ecl = tid >> 6, eb = tid & 63;   // epilogue (col, batch)
        float bia[2][3];
        #pragma unroll
        for (int l = 0; l < 2; ++l) {
            const float* bih = l ? b_ih1 : b_ih0;
            const float* bhh = l ? b_hh1 : b_hh0;
            #pragma unroll
            for (int g = 0; g < 3; ++g) {
                int row = gbase[g] + c0 + ecl;
                bia[l][g] = bih[row] + bhh[row];
            }
        }
        {   // x0 = [u0,w0,K] @ W_in.T + b_in, tiled layout
            int c = c0 + ecl;
            float v = u0[eb] * W_in[c * 3 + 0] + w0[eb] * W_in[c * 3 + 1]
                    + Kc[eb] * W_in[c * 3 + 2] + b_in[c];
            g_x[0][G(eb, c)] = v;
        }
        uint sticky = 1u;
        __syncthreads();
        if (tid == 0) publish(&g_flags[cta], 1u | (sticky << 16));

        const int lane = tid & 31;
        const int e = tid >> 5;             // k-eighth (warp)
        const int kb0 = e * 16;
        const int b0 = 2 * lane;
        const int sofs = sw16(b0) * 16;     // b0 pair slots: sofs, sofs^16

        int lyr = 0;
        bool done = false;
        #pragma unroll 1
        for (int t = 0; t < T && !done; ++t) {
            #pragma unroll
            for (int l = 0; l < 2; ++l) {
                uint php = (uint)(lyr + 1);       // producers' phase
                if (e == 0) poll_full(php, spub);
                else        warp_poll16(e, php);

                float oldh = 0.f;
                if (l == 1)
                    oldh = __ldcg(&g_x[t & 1][G(eb, c0 + ecl)]);

                const char* xb = (const char*)(l ? g_h0 : g_x[t & 1]);
                ull a0[12], a1[12];
                #pragma unroll
                for (int j = 0; j < 12; ++j) { a0[j] = 0; a1[j] = 0; }
                const ulonglong2* wrow = Wsm + l * 12 * 128;
                #pragma unroll 4
                for (int kb = kb0; kb < kb0 + 16; ++kb) {
                    ulonglong2 xv0 = __ldcg((const ulonglong2*)(xb + kb * 1024 + sofs));
                    ulonglong2 xv1 = __ldcg((const ulonglong2*)(xb + kb * 1024 + (sofs ^ 16)));
                    #pragma unroll
                    for (int j = 0; j < 12; ++j) {
                        ulonglong2 wv = wrow[j * 128 + kb];
                        a0[j] = fma2(xv0.x, wv.x, a0[j]);
                        a0[j] = fma2(xv0.y, wv.y, a0[j]);
                        a1[j] = fma2(xv1.x, wv.x, a1[j]);
                        a1[j] = fma2(xv1.y, wv.y, a1[j]);
                    }
                }
                __syncthreads();
                uint conv = *spub;            // warp0 wrote it pre-compute
                #pragma unroll
                for (int j = 0; j < 12; ++j) {
                    float f0, f1, f2, f3;
                    unpack2(a0[j], f0, f1);
                    unpack2(a1[j], f2, f3);
                    *(float2*)&red[j * 512 + e * 64 + b0] = make_float2(f0 + f1, f2 + f3);
                }
                __syncthreads();
                {   // epilogue: thread (ecl, eb) sums 8 partials x 3 gates
                    float s[3];
                    #pragma unroll
                    for (int g = 0; g < 3; ++g) {
                        const float* r = &red[(g * 4 + ecl) * 512 + eb];
                        float v = r[0];
                        #pragma unroll
                        for (int q = 1; q < 8; ++q) v += r[q * 64];
                        s[g] = v + bia[l][g];
                    }
                    float h = sigm(s[2]) * tanh_(sigm(s[0]) * tanh_(s[1]));
                    float* dst = l ? g_x[(t + 1) & 1] : g_h0;
                    dst[G(eb, c0 + ecl)] = h;
                    if (l == 1 && h != oldh) *sflag = 1u;
                }
                done = (l == 0 && t > 0 && conv == 0u);   // step t-1 was a fixed point
                __syncthreads();
                if (tid == 0) {
                    if (l == 1) { sticky = *sflag; *sflag = 0u; }
                    if (done) {
                        asm volatile("st.relaxed.gpu.u32 [%0], %1;"
                                     :: "l"(&g_tconv), "r"((uint)(t - 1)) : "memory");
                        publish(&g_flags[cta], 0xFFFFu);   // freeze
                    } else {
                        publish(&g_flags[cta], (uint)(lyr + 2) | (sticky << 16));
                    }
                }
                if (done) break;
                lyr++;
            }
        }
    } else {
        // ========================= output CTA =========================
        float* Wof = (float*)smem;            // [2][512]
        float* red2 = (float*)(smem + 8192);  // [2][64]
        for (int i = tid; i < 2 * H; i += NT) {
            int o = i >> 9, c = i & (H - 1);
            Wof[i] = o ? W_w[c] : W_u[c];
        }
        const int b = tid & 63;
        const int o = (tid >> 6) & 1;
        const int q = tid >> 7;               // c-half
        const float bias = o ? b_w[0] : b_u[0];
        __syncthreads();
        if (tid == 0) publish(&g_flags[NWORK], 5u);

        const int swb = sw16(b) << 2;
        #pragma unroll 1
        for (int t = 0; t < T; ++t) {
            uint ph = 3u + 2u * (uint)t;      // layer-1 phase of step t
            if (tid < 32) poll_full(ph, spub);
            if (tid == 0) {
                uint tc;
                asm volatile("ld.relaxed.gpu.u32 %0, [%1];" : "=r"(tc) : "l"(&g_tconv) : "memory");
                *stcv = tc;
            }
            __syncthreads();
            bool fin = ((uint)(t + 1) >= *stcv) || (t == T - 1);
            const float* hx = g_x[(t + 1) & 1];   // h1_t
            ull acc = 0;
            #pragma unroll 8
            for (int c = q * 256; c < q * 256 + 256; c += 4) {
                ulonglong2 hv = __ldcg((const ulonglong2*)(hx + ((c >> 2) << 8) + swb));
                ulonglong2 wv = *(const ulonglong2*)(Wof + o * H + c);
                acc = fma2(hv.x, wv.x, acc);
                acc = fma2(hv.y, wv.y, acc);
            }
            float lo, hi;
            unpack2(acc, lo, hi);
            float hs = lo + hi;
            if (q) red2[o * 64 + b] = hs;
            __syncthreads();
            if (!q) {
                hs += red2[o * 64 + b] + bias;
                float* ob = out + o * (B * T);    // us then ws, each [B][T]
                ob[b * T + t] = hs;
                if (fin) {
                    for (int tau = t + 1; tau < T; ++tau) ob[b * T + tau] = hs;
                }
            }
            __syncthreads();
            if (tid == 0)
                publish(&g_flags[NWORK], fin ? 0xFFFFu : (2u * (uint)t + 7u));
            if (fin) break;
        }
    }

    final_barrier();
    if (tid == 0) {
        asm volatile("st.relaxed.gpu.u32 [%0], %1;"
                     :: "l"(&g_flags[cta]), "r"(0u) : "memory");
        if (cta == 0)
            asm volatile("st.relaxed.gpu.u32 [%0], %1;"
                         :: "l"(&g_tconv), "r"(0x7FFFFFFFu) : "memory");
    }
}

extern "C" void kernel_launch(void* const* d_in, const int* in_sizes, int n_in,
                              void* d_out, int out_size) {
    (void)in_sizes; (void)n_in; (void)out_size;
    cudaFuncSetAttribute(fhn_kernel, cudaFuncAttributeMaxDynamicSharedMemorySize,
                         (int)SMEM_BYTES);
    fhn_kernel<<<NCTA, NT, SMEM_BYTES>>>(
        (const float*)d_in[0],   // u0
        (const float*)d_in[1],   // w0
        (const float*)d_in[2],   // K
        (const float*)d_in[3],   // W_in
        (const float*)d_in[4],   // b_in
        (const float*)d_in[5],   // W_ih0   (W_hh0 @6 unused)
        (const float*)d_in[7],   // b_ih0
        (const float*)d_in[8],   // b_hh0
        (const float*)d_in[9],   // W_ih1   (W_hh1 @10 unused)
        (const float*)d_in[11],  // b_ih1
        (const float*)d_in[12],  // b_hh1
        (const float*)d_in[13],  // W_u
        (const float*)d_in[14],  // b_u
        (const float*)d_in[15],  // W_w
        (const float*)d_in[16],  // b_w
        (float*)d_out);
}